// round 2
// baseline (speedup 1.0000x reference)
#include <cuda_runtime.h>
#include <cstdint>
#include <cstdio>

#define T_STEPS 512
#define BATCH   512
#define OBS_D   128
#define HID     128
#define ACT     18
#define TBROWS  (T_STEPS * BATCH)   // 262144

// Scratch (device globals: allocation is forbidden)
__device__ float g_emb[(size_t)TBROWS * HID];        // 128 MB
__device__ float g_gi [(size_t)TBROWS * 3 * HID];    // 384 MB

typedef unsigned long long u64;

__device__ __forceinline__ u64 pk2(float x) {
    u64 d; asm("mov.b64 %0, {%1,%1};" : "=l"(d) : "f"(x)); return d;
}
__device__ __forceinline__ void fma2(u64 &c, u64 a, u64 b) {
    asm("fma.rn.f32x2 %0, %1, %2, %3;" : "=l"(c) : "l"(a), "l"(b), "l"(c));
}
__device__ __forceinline__ float2 unpk(u64 v) {
    float2 f; asm("mov.b64 {%0,%1}, %2;" : "=f"(f.x), "=f"(f.y) : "l"(v)); return f;
}

// ---------------------------------------------------------------------------
// GEMM: C[M,N] = act(A[M,128] @ W[128,N] + bias[N]).  Tile 64x128, K=128 full.
// 256 threads, thread tile 4 rows x 8 cols, accumulators packed f32x2.
// ---------------------------------------------------------------------------
template<bool RELU>
__global__ __launch_bounds__(256, 2) void gemm_k128(
    const float* __restrict__ A, const float* __restrict__ W,
    const float* __restrict__ bias, float* __restrict__ C, int N)
{
    extern __shared__ float sm[];
    float* As = sm;            // [128][68]  As[k*68+m], transposed, padded
    float* Bs = sm + 128 * 68; // [128][128] Bs[k*128+n]

    const int m0  = blockIdx.x * 64;
    const int n0  = blockIdx.y * 128;
    const int tid = threadIdx.x;

    // Load A tile (coalesced 512B/warp), store transposed
    {
        const int k4 = (tid & 31) * 4;
        const int mb = tid >> 5;
        #pragma unroll
        for (int mm = mb; mm < 64; mm += 8) {
            float4 v = *(const float4*)(A + (size_t)(m0 + mm) * 128 + k4);
            As[(k4 + 0) * 68 + mm] = v.x;
            As[(k4 + 1) * 68 + mm] = v.y;
            As[(k4 + 2) * 68 + mm] = v.z;
            As[(k4 + 3) * 68 + mm] = v.w;
        }
    }
    // Load B tile
    {
        const int n4 = (tid & 31) * 4;
        const int kb = tid >> 5;
        #pragma unroll
        for (int kk = kb; kk < 128; kk += 8) {
            *(float4*)(Bs + kk * 128 + n4) =
                *(const float4*)(W + (size_t)kk * N + n0 + n4);
        }
    }
    __syncthreads();

    const int tx = tid & 15;   // col group: n = tx*8
    const int ty = tid >> 4;   // row group: m = ty*4

    u64 acc[4][4];             // [row][col-pair], each = packed (c, c+1)
    #pragma unroll
    for (int i = 0; i < 4; i++)
        #pragma unroll
        for (int j = 0; j < 4; j++) acc[i][j] = 0ull;

    const float* ap = As + ty * 4;
    const u64*   bp = (const u64*)Bs + tx * 4;   // row stride = 64 u64

    #pragma unroll 8
    for (int k = 0; k < 128; ++k) {
        float4 av = *(const float4*)(ap + k * 68);
        ulonglong2 b01 = *(const ulonglong2*)(bp + k * 64);
        ulonglong2 b23 = *(const ulonglong2*)(bp + k * 64 + 2);
        u64 a0 = pk2(av.x), a1 = pk2(av.y), a2 = pk2(av.z), a3 = pk2(av.w);
        fma2(acc[0][0], a0, b01.x); fma2(acc[0][1], a0, b01.y);
        fma2(acc[0][2], a0, b23.x); fma2(acc[0][3], a0, b23.y);
        fma2(acc[1][0], a1, b01.x); fma2(acc[1][1], a1, b01.y);
        fma2(acc[1][2], a1, b23.x); fma2(acc[1][3], a1, b23.y);
        fma2(acc[2][0], a2, b01.x); fma2(acc[2][1], a2, b01.y);
        fma2(acc[2][2], a2, b23.x); fma2(acc[2][3], a2, b23.y);
        fma2(acc[3][0], a3, b01.x); fma2(acc[3][1], a3, b01.y);
        fma2(acc[3][2], a3, b23.x); fma2(acc[3][3], a3, b23.y);
    }

    // Epilogue
    float bb[8];
    {
        float4 b0 = *(const float4*)(bias + n0 + tx * 8);
        float4 b1 = *(const float4*)(bias + n0 + tx * 8 + 4);
        bb[0]=b0.x; bb[1]=b0.y; bb[2]=b0.z; bb[3]=b0.w;
        bb[4]=b1.x; bb[5]=b1.y; bb[6]=b1.z; bb[7]=b1.w;
    }
    #pragma unroll
    for (int mi = 0; mi < 4; ++mi) {
        float2 f01 = unpk(acc[mi][0]);
        float2 f23 = unpk(acc[mi][1]);
        float2 f45 = unpk(acc[mi][2]);
        float2 f67 = unpk(acc[mi][3]);
        float v[8] = { f01.x, f01.y, f23.x, f23.y, f45.x, f45.y, f67.x, f67.y };
        #pragma unroll
        for (int j = 0; j < 8; ++j) {
            v[j] += bb[j];
            if (RELU) v[j] = fmaxf(v[j], 0.0f);
        }
        float* cp = C + (size_t)(m0 + ty * 4 + mi) * N + n0 + tx * 8;
        *(float4*)(cp)     = make_float4(v[0], v[1], v[2], v[3]);
        *(float4*)(cp + 4) = make_float4(v[4], v[5], v[6], v[7]);
    }
}

// ---------------------------------------------------------------------------
// Scan kernel: 128 CTAs x 384 threads. CTA owns 4 batch rows; iterates T=512
// steps with Wh resident in smem. Fuses GRU gates + output projection (q) and
// writes h_final. dones-reset folded in as multiplicative masks (gh and z*h).
// dones arrives as int32 (bool widened by the harness).
// ---------------------------------------------------------------------------
__global__ __launch_bounds__(384, 1) void scan_kernel(
    const float* __restrict__ hidden, const float* __restrict__ gi_all,
    const int* __restrict__ dones,
    const float* __restrict__ Wh, const float* __restrict__ bhn,
    const float* __restrict__ Wout, const float* __restrict__ bout,
    float* __restrict__ hfinal, float* __restrict__ q_out)
{
    extern __shared__ float sm[];
    float* Wh_s  = sm;                  // 49152 : Wh_s[k*384 + j]
    float* h_s   = Wh_s + 49152;        // 4*132 = 528
    float* gh_s  = h_s + 528;           // 4*388 = 1552 (pitch 388 de-conflicts)
    float* gi_s  = gh_s + 1552;         // 4*388 = 1552
    float* Wo_s  = gi_s + 1552;         // 128*20 = 2560 : Wo_s[k*20 + a]
    float* bhn_s = Wo_s + 2560;         // 128
    float* bo_s  = bhn_s + 128;         // 20
    float* mask_s= bo_s + 20;           // 4

    const int tid = threadIdx.x;        // 0..383
    const int r   = tid & 3;            // batch row within CTA
    const int jg  = tid >> 2;           // 0..95 : cols jg*4 .. jg*4+3
    const int b0  = blockIdx.x * 4;

    // Stage weights
    for (int i = tid; i < 49152 / 4; i += 384)
        ((float4*)Wh_s)[i] = ((const float4*)Wh)[i];
    for (int i = tid; i < 128 * 18; i += 384)
        Wo_s[(i / 18) * 20 + (i % 18)] = Wout[i];
    if (tid < 128) bhn_s[tid] = bhn[tid];
    if (tid < 18)  bo_s[tid]  = bout[tid];
    for (int i = tid; i < 512; i += 384)
        h_s[(i >> 7) * 132 + (i & 127)] = hidden[b0 * 128 + i];
    __syncthreads();

    const float* gip = gi_all + (size_t)(b0 + r) * 384 + jg * 4;
    float4 gi_cur = *(const float4*)(gip);   // t = 0

    for (int t = 0; t < T_STEPS; ++t) {
        const float mask = (dones[t * BATCH + b0 + r] != 0) ? 0.0f : 1.0f;
        if (jg == 0) mask_s[r] = mask;

        // Prefetch next step's gi early (hidden under the gh matvec)
        float4 gi_next = gi_cur;
        if (t + 1 < T_STEPS)
            gi_next = *(const float4*)(gip + (size_t)(t + 1) * (BATCH * 384));

        // gh[r][jg*4 .. +3] = h[r] . Wh[:, j]   (packed f32x2 accumulate)
        u64 a01 = 0ull, a23 = 0ull;
        {
            const u64*   wp = (const u64*)Wh_s + jg * 2;   // row stride 192 u64
            const float* hp = h_s + r * 132;
            #pragma unroll 16
            for (int k = 0; k < 128; ++k) {
                u64 hv = pk2(hp[k]);
                ulonglong2 w = *(const ulonglong2*)(wp + (size_t)k * 192);
                fma2(a01, hv, w.x);
                fma2(a23, hv, w.y);
            }
        }
        {
            float2 f01 = unpk(a01), f23 = unpk(a23);
            *(float4*)(gh_s + r * 388 + jg * 4) =
                make_float4(f01.x * mask, f01.y * mask, f23.x * mask, f23.y * mask);
            *(float4*)(gi_s + r * 388 + jg * 4) = gi_cur;
        }
        gi_cur = gi_next;
        __syncthreads();   // (A) gh_s / gi_s / mask_s ready

        // Gate math: 512 items (4 rows x 128) over 384 threads
        float hn0, hn1 = 0.0f;
        {
            const int rr = tid >> 7, i = tid & 127;
            const float* gr = gi_s + rr * 388;
            const float* hr = gh_s + rr * 388;
            float xr = gr[i]       + hr[i];
            float xz = gr[128 + i] + hr[128 + i];
            float rg = 1.0f / (1.0f + expf(-xr));
            float zg = 1.0f / (1.0f + expf(-xz));
            float nv = tanhf(gr[256 + i] + rg * (hr[256 + i] + bhn_s[i]));
            float hv = h_s[rr * 132 + i] * mask_s[rr];
            hn0 = (1.0f - zg) * nv + zg * hv;
        }
        if (tid < 128) {
            const int rr = 3, i = tid;
            const float* gr = gi_s + rr * 388;
            const float* hr = gh_s + rr * 388;
            float xr = gr[i]       + hr[i];
            float xz = gr[128 + i] + hr[128 + i];
            float rg = 1.0f / (1.0f + expf(-xr));
            float zg = 1.0f / (1.0f + expf(-xz));
            float nv = tanhf(gr[256 + i] + rg * (hr[256 + i] + bhn_s[i]));
            float hv = h_s[rr * 132 + i] * mask_s[rr];
            hn1 = (1.0f - zg) * nv + zg * hv;
        }
        __syncthreads();   // (B) everyone finished reading old h_s

        h_s[(tid >> 7) * 132 + (tid & 127)] = hn0;
        if (tid < 128) h_s[3 * 132 + tid] = hn1;
        __syncthreads();   // (C) new h ready

        // q[t, b0+rr, a] = h_new . W_out[:, a] + b_out[a]
        if (tid < 72) {
            const int rr = tid / 18, a = tid % 18;
            float acc = bo_s[a];
            const float* hq = h_s + rr * 132;
            #pragma unroll 8
            for (int k = 0; k < 128; ++k)
                acc += hq[k] * Wo_s[k * 20 + a];
            q_out[((size_t)t * BATCH + b0 + rr) * ACT + a] = acc;
        }
    }

    // h_final
    for (int i = tid; i < 512; i += 384)
        hfinal[b0 * 128 + i] = h_s[(i >> 7) * 132 + (i & 127)];
}

// ---------------------------------------------------------------------------
extern "C" void kernel_launch(void* const* d_in, const int* in_sizes, int n_in,
                              void* d_out, int out_size)
{
    const float* hidden = (const float*)d_in[0];
    const float* obs    = (const float*)d_in[1];
    const int*   dones  = (const int*)d_in[2];
    const float* W_emb  = (const float*)d_in[3];
    const float* b_emb  = (const float*)d_in[4];
    const float* Wi     = (const float*)d_in[5];
    const float* bi     = (const float*)d_in[6];
    const float* Wh     = (const float*)d_in[7];
    const float* bhn    = (const float*)d_in[8];
    const float* W_out  = (const float*)d_in[9];
    const float* b_out  = (const float*)d_in[10];

    float* out    = (float*)d_out;
    float* hfinal = out;                        // [512, 128]
    float* q      = out + (size_t)BATCH * HID;  // [512, 512, 18]

    void *p_emb, *p_gi;
    cudaGetSymbolAddress(&p_emb, g_emb);
    cudaGetSymbolAddress(&p_gi,  g_gi);
    float* emb = (float*)p_emb;
    float* gi  = (float*)p_gi;

    const int gemm_smem = (128 * 68 + 128 * 128) * 4;   // 100352 B
    const int scan_smem = 55496 * 4;                    // 221984 B
    cudaFuncSetAttribute(gemm_k128<true>,
        cudaFuncAttributeMaxDynamicSharedMemorySize, gemm_smem);
    cudaFuncSetAttribute(gemm_k128<false>,
        cudaFuncAttributeMaxDynamicSharedMemorySize, gemm_smem);
    cudaFuncSetAttribute(scan_kernel,
        cudaFuncAttributeMaxDynamicSharedMemorySize, scan_smem);

    // emb = relu(obs @ W_emb + b_emb)
    gemm_k128<true><<<dim3(TBROWS / 64, 1), 256, gemm_smem>>>(obs, W_emb, b_emb, emb, 128);
    // gi = emb @ Wi + bi
    gemm_k128<false><<<dim3(TBROWS / 64, 3), 256, gemm_smem>>>(emb, Wi, bi, gi, 384);
    // scan (fused GRU + output projection)
    scan_kernel<<<BATCH / 4, 384, scan_smem>>>(hidden, gi, dones, Wh, bhn,
                                               W_out, b_out, hfinal, q);
}

// round 3
// speedup vs baseline: 1.2506x; 1.2506x over previous
#include <cuda_runtime.h>
#include <cstdint>

#define T_STEPS 512
#define BATCH   512
#define HID     128
#define ACT     18
#define TBROWS  (T_STEPS * BATCH)   // 262144

// Scratch (device globals: allocation is forbidden)
__device__ float g_ys[(size_t)TBROWS * HID];         // emb, then ys (reused)
__device__ float g_gi [(size_t)TBROWS * 3 * HID];    // gi

typedef unsigned long long u64;

__device__ __forceinline__ u64 pk2(float x) {
    u64 d; asm("mov.b64 %0, {%1,%1};" : "=l"(d) : "f"(x)); return d;
}
__device__ __forceinline__ u64 pk2two(float a, float b) {
    u64 d; asm("mov.b64 %0, {%1,%2};" : "=l"(d) : "f"(a), "f"(b)); return d;
}
__device__ __forceinline__ void fma2(u64 &c, u64 a, u64 b) {
    asm("fma.rn.f32x2 %0, %1, %2, %3;" : "=l"(c) : "l"(a), "l"(b), "l"(c));
}
__device__ __forceinline__ float2 unpk(u64 v) {
    float2 f; asm("mov.b64 {%0,%1}, %2;" : "=f"(f.x), "=f"(f.y) : "l"(v)); return f;
}

// ---------------------------------------------------------------------------
// GEMM: C[M,N] = act(A[M,128] @ W[128,N] + bias[N]).
// CTA tile 64x128, 128 threads, thread tile 8x8, f32x2 accumulators.
// A kept row-major (pitch 129 -> conflict-free broadcast reads),
// B row-major [k][n] read as packed col-pairs (no packing movs).
// ---------------------------------------------------------------------------
template<bool RELU>
__global__ __launch_bounds__(128, 2) void gemm8x8(
    const float* __restrict__ A, const float* __restrict__ W,
    const float* __restrict__ bias, float* __restrict__ C, int N)
{
    extern __shared__ float sm[];
    float* As = sm;             // [64][129]
    float* Bs = sm + 64 * 129;  // [128][128]

    const int m0  = blockIdx.x * 64;
    const int n0  = blockIdx.y * 128;
    const int tid = threadIdx.x;

    // Load A tile: 64 rows x 128 k (coalesced global, scalar smem stores)
    for (int i = tid; i < 2048; i += 128) {
        int m = i >> 5, kv = (i & 31) << 2;
        float4 v = *(const float4*)(A + (size_t)(m0 + m) * 128 + kv);
        float* d = As + m * 129 + kv;
        d[0] = v.x; d[1] = v.y; d[2] = v.z; d[3] = v.w;
    }
    // Load B tile: 128 k x 128 n
    for (int i = tid; i < 4096; i += 128) {
        int k = i >> 5, nv = (i & 31) << 2;
        *(float4*)(Bs + k * 128 + nv) =
            *(const float4*)(W + (size_t)k * N + n0 + nv);
    }
    __syncthreads();

    const int tx = tid & 15;   // cols n0 + tx*8 .. +7
    const int ty = tid >> 4;   // rows m0 + ty*8 .. +7

    u64 acc[8][4];
    #pragma unroll
    for (int r = 0; r < 8; ++r)
        #pragma unroll
        for (int c = 0; c < 4; ++c) acc[r][c] = 0ull;

    const float* ap = As + ty * 8 * 129;
    const float* bp = Bs + tx * 8;

    #pragma unroll 4
    for (int k = 0; k < 128; ++k) {
        u64 ad[8];
        #pragma unroll
        for (int r = 0; r < 8; ++r) ad[r] = pk2(ap[r * 129 + k]);
        ulonglong2 b01 = *(const ulonglong2*)(bp + (size_t)k * 128);
        ulonglong2 b23 = *(const ulonglong2*)(bp + (size_t)k * 128 + 4);
        #pragma unroll
        for (int r = 0; r < 8; ++r) {
            fma2(acc[r][0], ad[r], b01.x);
            fma2(acc[r][1], ad[r], b01.y);
            fma2(acc[r][2], ad[r], b23.x);
            fma2(acc[r][3], ad[r], b23.y);
        }
    }

    float bb[8];
    {
        float4 b0 = *(const float4*)(bias + n0 + tx * 8);
        float4 b1 = *(const float4*)(bias + n0 + tx * 8 + 4);
        bb[0]=b0.x; bb[1]=b0.y; bb[2]=b0.z; bb[3]=b0.w;
        bb[4]=b1.x; bb[5]=b1.y; bb[6]=b1.z; bb[7]=b1.w;
    }
    #pragma unroll
    for (int r = 0; r < 8; ++r) {
        float2 f0 = unpk(acc[r][0]), f1 = unpk(acc[r][1]);
        float2 f2 = unpk(acc[r][2]), f3 = unpk(acc[r][3]);
        float v[8] = { f0.x, f0.y, f1.x, f1.y, f2.x, f2.y, f3.x, f3.y };
        #pragma unroll
        for (int j = 0; j < 8; ++j) {
            v[j] += bb[j];
            if (RELU) v[j] = fmaxf(v[j], 0.0f);
        }
        float* cp = C + (size_t)(m0 + ty * 8 + r) * N + n0 + tx * 8;
        *(float4*)(cp)     = make_float4(v[0], v[1], v[2], v[3]);
        *(float4*)(cp + 4) = make_float4(v[4], v[5], v[6], v[7]);
    }
}

// ---------------------------------------------------------------------------
// Scan: 128 CTAs x 384 threads, 4 batch rows per CTA, Wh resident in smem.
// Thread j computes gh column j for ALL 4 rows (h4 broadcast, w coalesced).
// Writes ys to global; q projection is a separate GEMM afterwards.
// ---------------------------------------------------------------------------
__device__ __forceinline__ float sigf(float x) {
    return __fdividef(1.0f, 1.0f + __expf(-x));
}
__device__ __forceinline__ float tanhfast(float x) {
    return __fdividef(2.0f, 1.0f + __expf(-2.0f * x)) - 1.0f;
}

__global__ __launch_bounds__(384, 1) void scan_kernel(
    const float* __restrict__ hidden, const float* __restrict__ gi_all,
    const int* __restrict__ dones,
    const float* __restrict__ Wh, const float* __restrict__ bhn,
    float* __restrict__ hfinal, float* __restrict__ ys)
{
    extern __shared__ float sm[];
    float*  Wh_s   = sm;                          // [128][384] = 196608 B
    float4* h4_s   = (float4*)(sm + 49152);       // [128] (h of 4 rows per dim)
    u64*    gh01_s = (u64*)(sm + 49152 + 512);    // [384] rows 0,1 packed
    u64*    gh23_s = gh01_s + 384;                // [384] rows 2,3 packed
    float*  bhn_s  = (float*)(gh23_s + 384);      // [128]

    const int tid = threadIdx.x;
    const int b0  = blockIdx.x * 4;

    // Stage Wh + bhn
    for (int i = tid; i < 12288; i += 384)
        ((float4*)Wh_s)[i] = ((const float4*)Wh)[i];
    if (tid < 128) bhn_s[tid] = bhn[tid];
    // Initial h
    for (int idx = tid; idx < 512; idx += 384) {
        int r = idx >> 7, i = idx & 127;
        ((float*)&h4_s[i])[r] = hidden[(size_t)(b0 + r) * 128 + i];
    }
    __syncthreads();

    // gate slot 0: all threads -> (rr0, i0); slot 1: tid<128 -> (3, tid)
    const int rr0 = tid >> 7;
    const int i0  = tid & 127;

    const float* wp = Wh_s + tid;

    for (int t = 0; t < T_STEPS; ++t) {
        // ---- prefetch gi + dones for this step (consumed after sync A) ----
        const size_t grow0 = ((size_t)t * BATCH + b0 + rr0) * 384;
        float gr0 = gi_all[grow0 + i0];
        float gz0 = gi_all[grow0 + 128 + i0];
        float gn0 = gi_all[grow0 + 256 + i0];
        float mk0 = dones[t * BATCH + b0 + rr0] ? 0.0f : 1.0f;
        float gr1 = 0.f, gz1 = 0.f, gn1 = 0.f, mk1 = 0.f;
        if (tid < 128) {
            const size_t grow1 = ((size_t)t * BATCH + b0 + 3) * 384;
            gr1 = gi_all[grow1 + tid];
            gz1 = gi_all[grow1 + 128 + tid];
            gn1 = gi_all[grow1 + 256 + tid];
            mk1 = dones[t * BATCH + b0 + 3] ? 0.0f : 1.0f;
        }

        // ---- matvec: gh[:, tid] = h4 . Wh[:, tid] ----
        u64 a01 = 0ull, a23 = 0ull;
        #pragma unroll 16
        for (int k = 0; k < 128; ++k) {
            ulonglong2 hv = *(const ulonglong2*)&h4_s[k];
            u64 wd = pk2(wp[(size_t)k * 384]);
            fma2(a01, hv.x, wd);
            fma2(a23, hv.y, wd);
        }
        gh01_s[tid] = a01;
        gh23_s[tid] = a23;
        __syncthreads();   // (A) gh ready; all matvec reads of h4 done

        // ---- gates slot 0 ----
        {
            const int rr = rr0, i = i0;
            const float* g = (rr < 2) ? (const float*)gh01_s : (const float*)gh23_s;
            const int sub = rr & 1;
            float ghr = g[2 * i + sub];
            float ghz = g[2 * (128 + i) + sub];
            float ghn = g[2 * (256 + i) + sub];
            float rg = sigf(gr0 + mk0 * ghr);
            float zg = sigf(gz0 + mk0 * ghz);
            float nv = tanhfast(gn0 + rg * (mk0 * ghn + bhn_s[i]));
            float* hp = ((float*)&h4_s[i]) + rr;
            float hold = *hp * mk0;
            float hn = (1.0f - zg) * nv + zg * hold;
            *hp = hn;
            ys[((size_t)t * BATCH + b0 + rr) * 128 + i] = hn;
        }
        // ---- gates slot 1 (row 3) ----
        if (tid < 128) {
            const int i = tid;
            const float* g = (const float*)gh23_s;
            float ghr = g[2 * i + 1];
            float ghz = g[2 * (128 + i) + 1];
            float ghn = g[2 * (256 + i) + 1];
            float rg = sigf(gr1 + mk1 * ghr);
            float zg = sigf(gz1 + mk1 * ghz);
            float nv = tanhfast(gn1 + rg * (mk1 * ghn + bhn_s[i]));
            float* hp = ((float*)&h4_s[i]) + 3;
            float hold = *hp * mk1;
            float hn = (1.0f - zg) * nv + zg * hold;
            *hp = hn;
            ys[((size_t)t * BATCH + b0 + 3) * 128 + i] = hn;
        }
        __syncthreads();   // (B) h4 updated before next matvec
    }

    for (int idx = tid; idx < 512; idx += 384) {
        int r = idx >> 7, i = idx & 127;
        hfinal[(size_t)(b0 + r) * 128 + i] = ((float*)&h4_s[i])[r];
    }
}

// ---------------------------------------------------------------------------
// q projection: q[M,18] = ys[M,128] @ W_out[128,18] + b_out.  256 rows/CTA,
// one thread per row, 9 packed col-pair accumulators.
// ---------------------------------------------------------------------------
__global__ __launch_bounds__(256, 1) void qproj_kernel(
    const float* __restrict__ ys, const float* __restrict__ Wo,
    const float* __restrict__ bo, float* __restrict__ q)
{
    extern __shared__ float sm[];
    float* As   = sm;                 // [256][129]
    float* Wo_s = sm + 256 * 129;     // [128][20]
    float* bo_s = Wo_s + 128 * 20;    // [18]

    const int tid = threadIdx.x;
    const size_t m0 = (size_t)blockIdx.x * 256;

    for (int i = tid; i < 8192; i += 256) {
        int m = i >> 5, kv = (i & 31) << 2;
        float4 v = *(const float4*)(ys + (m0 + m) * 128 + kv);
        float* d = As + m * 129 + kv;
        d[0] = v.x; d[1] = v.y; d[2] = v.z; d[3] = v.w;
    }
    for (int i = tid; i < 128 * 18; i += 256)
        Wo_s[(i / 18) * 20 + (i % 18)] = Wo[i];
    if (tid < 18) bo_s[tid] = bo[tid];
    __syncthreads();

    u64 acc[9];
    #pragma unroll
    for (int p = 0; p < 9; ++p) acc[p] = pk2two(bo_s[2 * p], bo_s[2 * p + 1]);

    const float* ap = As + tid * 129;
    #pragma unroll 4
    for (int k = 0; k < 128; ++k) {
        u64 hd = pk2(ap[k]);
        const u64* wrow = (const u64*)(Wo_s + k * 20);
        #pragma unroll
        for (int p = 0; p < 9; ++p) fma2(acc[p], hd, wrow[p]);
    }

    float* qp = q + (m0 + tid) * ACT;
    #pragma unroll
    for (int p = 0; p < 9; ++p) {
        float2 f = unpk(acc[p]);
        *(float2*)(qp + 2 * p) = f;
    }
}

// ---------------------------------------------------------------------------
extern "C" void kernel_launch(void* const* d_in, const int* in_sizes, int n_in,
                              void* d_out, int out_size)
{
    const float* hidden = (const float*)d_in[0];
    const float* obs    = (const float*)d_in[1];
    const int*   dones  = (const int*)d_in[2];
    const float* W_emb  = (const float*)d_in[3];
    const float* b_emb  = (const float*)d_in[4];
    const float* Wi     = (const float*)d_in[5];
    const float* bi     = (const float*)d_in[6];
    const float* Wh     = (const float*)d_in[7];
    const float* bhn    = (const float*)d_in[8];
    const float* W_out  = (const float*)d_in[9];
    const float* b_out  = (const float*)d_in[10];

    float* out    = (float*)d_out;
    float* hfinal = out;                        // [512, 128]
    float* q      = out + (size_t)BATCH * HID;  // [512, 512, 18]

    void *p_ys, *p_gi;
    cudaGetSymbolAddress(&p_ys, g_ys);
    cudaGetSymbolAddress(&p_gi, g_gi);
    float* embys = (float*)p_ys;   // emb, later ys
    float* gi    = (float*)p_gi;

    const int gemm_smem  = (64 * 129 + 128 * 128) * 4;          // 98816 B
    const int scan_smem  = (49152 + 512 + 768 * 2 + 128) * 4;   // 205312 B
    const int qproj_smem = (256 * 129 + 128 * 20 + 18) * 4;     // 142408 B
    cudaFuncSetAttribute(gemm8x8<true>,
        cudaFuncAttributeMaxDynamicSharedMemorySize, gemm_smem);
    cudaFuncSetAttribute(gemm8x8<false>,
        cudaFuncAttributeMaxDynamicSharedMemorySize, gemm_smem);
    cudaFuncSetAttribute(scan_kernel,
        cudaFuncAttributeMaxDynamicSharedMemorySize, scan_smem);
    cudaFuncSetAttribute(qproj_kernel,
        cudaFuncAttributeMaxDynamicSharedMemorySize, qproj_smem);

    // emb = relu(obs @ W_emb + b_emb)
    gemm8x8<true><<<dim3(TBROWS / 64, 1), 128, gemm_smem>>>(obs, W_emb, b_emb, embys, 128);
    // gi = emb @ Wi + bi
    gemm8x8<false><<<dim3(TBROWS / 64, 3), 128, gemm_smem>>>(embys, Wi, bi, gi, 384);
    // GRU scan (writes ys over emb buffer)
    scan_kernel<<<BATCH / 4, 384, scan_smem>>>(hidden, gi, dones, Wh, bhn,
                                               hfinal, embys);
    // q = ys @ W_out + b_out
    qproj_kernel<<<TBROWS / 256, 256, qproj_smem>>>(embys, W_out, b_out, q);
}

// round 4
// speedup vs baseline: 1.3446x; 1.0752x over previous
#include <cuda_runtime.h>
#include <cstdint>

#define T_STEPS 512
#define BATCH   512
#define HID     128
#define ACT     18
#define TBROWS  (T_STEPS * BATCH)   // 262144

// Scratch (device globals: allocation is forbidden)
__device__ float g_ys[(size_t)TBROWS * HID];         // emb, then ys (reused)
__device__ float g_gi [(size_t)TBROWS * 3 * HID];    // gi

typedef unsigned long long u64;

__device__ __forceinline__ u64 pk2(float x) {
    u64 d; asm("mov.b64 %0, {%1,%1};" : "=l"(d) : "f"(x)); return d;
}
__device__ __forceinline__ u64 pk2two(float a, float b) {
    u64 d; asm("mov.b64 %0, {%1,%2};" : "=l"(d) : "f"(a), "f"(b)); return d;
}
__device__ __forceinline__ void fma2(u64 &c, u64 a, u64 b) {
    asm("fma.rn.f32x2 %0, %1, %2, %3;" : "=l"(c) : "l"(a), "l"(b), "l"(c));
}
__device__ __forceinline__ float2 unpk(u64 v) {
    float2 f; asm("mov.b64 {%0,%1}, %2;" : "=f"(f.x), "=f"(f.y) : "l"(v)); return f;
}

// ---------------------------------------------------------------------------
// GEMM: C[M,N] = act(A[M,128] @ W[128,N] + bias[N]).
// CTA tile 64x128, 128 threads, thread tile 8x8, f32x2 accumulators.
// ---------------------------------------------------------------------------
template<bool RELU>
__global__ __launch_bounds__(128, 2) void gemm8x8(
    const float* __restrict__ A, const float* __restrict__ W,
    const float* __restrict__ bias, float* __restrict__ C, int N)
{
    extern __shared__ float sm[];
    float* As = sm;             // [64][129]
    float* Bs = sm + 64 * 129;  // [128][128]

    const int m0  = blockIdx.x * 64;
    const int n0  = blockIdx.y * 128;
    const int tid = threadIdx.x;

    for (int i = tid; i < 2048; i += 128) {
        int m = i >> 5, kv = (i & 31) << 2;
        float4 v = *(const float4*)(A + (size_t)(m0 + m) * 128 + kv);
        float* d = As + m * 129 + kv;
        d[0] = v.x; d[1] = v.y; d[2] = v.z; d[3] = v.w;
    }
    for (int i = tid; i < 4096; i += 128) {
        int k = i >> 5, nv = (i & 31) << 2;
        *(float4*)(Bs + k * 128 + nv) =
            *(const float4*)(W + (size_t)k * N + n0 + nv);
    }
    __syncthreads();

    const int tx = tid & 15;
    const int ty = tid >> 4;

    u64 acc[8][4];
    #pragma unroll
    for (int r = 0; r < 8; ++r)
        #pragma unroll
        for (int c = 0; c < 4; ++c) acc[r][c] = 0ull;

    const float* ap = As + ty * 8 * 129;
    const float* bp = Bs + tx * 8;

    #pragma unroll 4
    for (int k = 0; k < 128; ++k) {
        u64 ad[8];
        #pragma unroll
        for (int r = 0; r < 8; ++r) ad[r] = pk2(ap[r * 129 + k]);
        ulonglong2 b01 = *(const ulonglong2*)(bp + (size_t)k * 128);
        ulonglong2 b23 = *(const ulonglong2*)(bp + (size_t)k * 128 + 4);
        #pragma unroll
        for (int r = 0; r < 8; ++r) {
            fma2(acc[r][0], ad[r], b01.x);
            fma2(acc[r][1], ad[r], b01.y);
            fma2(acc[r][2], ad[r], b23.x);
            fma2(acc[r][3], ad[r], b23.y);
        }
    }

    float bb[8];
    {
        float4 b0 = *(const float4*)(bias + n0 + tx * 8);
        float4 b1 = *(const float4*)(bias + n0 + tx * 8 + 4);
        bb[0]=b0.x; bb[1]=b0.y; bb[2]=b0.z; bb[3]=b0.w;
        bb[4]=b1.x; bb[5]=b1.y; bb[6]=b1.z; bb[7]=b1.w;
    }
    #pragma unroll
    for (int r = 0; r < 8; ++r) {
        float2 f0 = unpk(acc[r][0]), f1 = unpk(acc[r][1]);
        float2 f2 = unpk(acc[r][2]), f3 = unpk(acc[r][3]);
        float v[8] = { f0.x, f0.y, f1.x, f1.y, f2.x, f2.y, f3.x, f3.y };
        #pragma unroll
        for (int j = 0; j < 8; ++j) {
            v[j] += bb[j];
            if (RELU) v[j] = fmaxf(v[j], 0.0f);
        }
        float* cp = C + (size_t)(m0 + ty * 8 + r) * N + n0 + tx * 8;
        *(float4*)(cp)     = make_float4(v[0], v[1], v[2], v[3]);
        *(float4*)(cp + 4) = make_float4(v[4], v[5], v[6], v[7]);
    }
}

// ---------------------------------------------------------------------------
// Scan: 128 CTAs x 384 threads, 4 batch rows per CTA.
// Wh column tid lives in REGISTERS (128 floats/thread) -> matvec does only a
// single broadcast LDS.128 per k. dones masks precomputed in smem.
// ---------------------------------------------------------------------------
__device__ __forceinline__ float sigf(float x) {
    return __fdividef(1.0f, 1.0f + __expf(-x));
}
__device__ __forceinline__ float tanhfast(float x) {
    return __fdividef(2.0f, 1.0f + __expf(-2.0f * x)) - 1.0f;
}

__global__ __launch_bounds__(384, 1) void scan_kernel(
    const float* __restrict__ hidden, const float* __restrict__ gi_all,
    const int* __restrict__ dones,
    const float* __restrict__ Wh, const float* __restrict__ bhn,
    float* __restrict__ hfinal, float* __restrict__ ys)
{
    __shared__ float4 h4_s[128];       // h of 4 rows per hidden dim
    __shared__ u64    gh01_s[384];     // gh rows 0,1 packed per column
    __shared__ u64    gh23_s[384];     // gh rows 2,3 packed per column
    __shared__ float  bhn_s[128];
    __shared__ float  maskf_s[T_STEPS * 4];   // 8KB: (1-done) per (t, row)

    const int tid = threadIdx.x;
    const int b0  = blockIdx.x * 4;

    // Wh column tid -> registers (coalesced LDG across threads)
    float w[128];
    #pragma unroll
    for (int k = 0; k < 128; ++k)
        w[k] = Wh[(size_t)k * 384 + tid];

    if (tid < 128) bhn_s[tid] = bhn[tid];
    for (int i = tid; i < T_STEPS * 4; i += 384) {
        int t = i >> 2, r = i & 3;
        maskf_s[i] = dones[t * BATCH + b0 + r] ? 0.0f : 1.0f;
    }
    for (int idx = tid; idx < 512; idx += 384) {
        int r = idx >> 7, i = idx & 127;
        ((float*)&h4_s[i])[r] = hidden[(size_t)(b0 + r) * 128 + i];
    }
    __syncthreads();

    const int rr0 = tid >> 7;
    const int i0  = tid & 127;

    for (int t = 0; t < T_STEPS; ++t) {
        // prefetch gi for this step (consumed after sync A)
        const size_t grow0 = ((size_t)t * BATCH + b0 + rr0) * 384;
        float gr0 = gi_all[grow0 + i0];
        float gz0 = gi_all[grow0 + 128 + i0];
        float gn0 = gi_all[grow0 + 256 + i0];
        float gr1 = 0.f, gz1 = 0.f, gn1 = 0.f;
        if (tid < 128) {
            const size_t grow1 = ((size_t)t * BATCH + b0 + 3) * 384;
            gr1 = gi_all[grow1 + tid];
            gz1 = gi_all[grow1 + 128 + tid];
            gn1 = gi_all[grow1 + 256 + tid];
        }

        // matvec: gh[:, tid] = h4 . w  (w in registers)
        u64 a01 = 0ull, a23 = 0ull;
        #pragma unroll
        for (int k = 0; k < 128; ++k) {
            ulonglong2 hv = *(const ulonglong2*)&h4_s[k];
            u64 wd = pk2(w[k]);
            fma2(a01, hv.x, wd);
            fma2(a23, hv.y, wd);
        }
        gh01_s[tid] = a01;
        gh23_s[tid] = a23;
        __syncthreads();   // (A) gh ready; all matvec reads of h4 done

        // gates slot 0: item (rr0, i0)
        {
            const float mk = maskf_s[t * 4 + rr0];
            const float* g = (rr0 < 2) ? (const float*)gh01_s : (const float*)gh23_s;
            const int sub = rr0 & 1;
            float ghr = g[2 * i0 + sub];
            float ghz = g[2 * (128 + i0) + sub];
            float ghn = g[2 * (256 + i0) + sub];
            float rg = sigf(gr0 + mk * ghr);
            float zg = sigf(gz0 + mk * ghz);
            float nv = tanhfast(gn0 + rg * (mk * ghn + bhn_s[i0]));
            float* hp = ((float*)&h4_s[i0]) + rr0;
            float hn = (1.0f - zg) * nv + zg * (*hp * mk);
            *hp = hn;
            ys[((size_t)t * BATCH + b0 + rr0) * 128 + i0] = hn;
        }
        // gates slot 1: row 3
        if (tid < 128) {
            const float mk = maskf_s[t * 4 + 3];
            const float* g = (const float*)gh23_s;
            float ghr = g[2 * tid + 1];
            float ghz = g[2 * (128 + tid) + 1];
            float ghn = g[2 * (256 + tid) + 1];
            float rg = sigf(gr1 + mk * ghr);
            float zg = sigf(gz1 + mk * ghz);
            float nv = tanhfast(gn1 + rg * (mk * ghn + bhn_s[tid]));
            float* hp = ((float*)&h4_s[tid]) + 3;
            float hn = (1.0f - zg) * nv + zg * (*hp * mk);
            *hp = hn;
            ys[((size_t)t * BATCH + b0 + 3) * 128 + tid] = hn;
        }
        __syncthreads();   // (B) h4 updated before next matvec
    }

    for (int idx = tid; idx < 512; idx += 384) {
        int r = idx >> 7, i = idx & 127;
        hfinal[(size_t)(b0 + r) * 128 + i] = ((float*)&h4_s[i])[r];
    }
}

// ---------------------------------------------------------------------------
// q projection: q[M,18] = ys[M,128] @ W_out[128,18] + b_out.
// 128 rows/CTA, 128 threads (1 row/thread), 2 CTAs/SM.
// ---------------------------------------------------------------------------
__global__ __launch_bounds__(128, 2) void qproj_kernel(
    const float* __restrict__ ys, const float* __restrict__ Wo,
    const float* __restrict__ bo, float* __restrict__ q)
{
    extern __shared__ float sm[];
    float* As   = sm;                 // [128][129]
    float* Wo_s = sm + 128 * 129;     // [128][20]
    float* bo_s = Wo_s + 128 * 20;    // [18]

    const int tid = threadIdx.x;
    const size_t m0 = (size_t)blockIdx.x * 128;

    for (int i = tid; i < 4096; i += 128) {
        int m = i >> 5, kv = (i & 31) << 2;
        float4 v = *(const float4*)(ys + (m0 + m) * 128 + kv);
        float* d = As + m * 129 + kv;
        d[0] = v.x; d[1] = v.y; d[2] = v.z; d[3] = v.w;
    }
    for (int i = tid; i < 128 * 18; i += 128)
        Wo_s[(i / 18) * 20 + (i % 18)] = Wo[i];
    if (tid < 18) bo_s[tid] = bo[tid];
    __syncthreads();

    u64 acc[9];
    #pragma unroll
    for (int p = 0; p < 9; ++p) acc[p] = pk2two(bo_s[2 * p], bo_s[2 * p + 1]);

    const float* ap = As + tid * 129;
    #pragma unroll 4
    for (int k = 0; k < 128; ++k) {
        u64 hd = pk2(ap[k]);
        const u64* wrow = (const u64*)(Wo_s + k * 20);
        #pragma unroll
        for (int p = 0; p < 9; ++p) fma2(acc[p], hd, wrow[p]);
    }

    float* qp = q + (m0 + tid) * ACT;
    #pragma unroll
    for (int p = 0; p < 9; ++p) {
        float2 f = unpk(acc[p]);
        *(float2*)(qp + 2 * p) = f;
    }
}

// ---------------------------------------------------------------------------
extern "C" void kernel_launch(void* const* d_in, const int* in_sizes, int n_in,
                              void* d_out, int out_size)
{
    const float* hidden = (const float*)d_in[0];
    const float* obs    = (const float*)d_in[1];
    const int*   dones  = (const int*)d_in[2];
    const float* W_emb  = (const float*)d_in[3];
    const float* b_emb  = (const float*)d_in[4];
    const float* Wi     = (const float*)d_in[5];
    const float* bi     = (const float*)d_in[6];
    const float* Wh     = (const float*)d_in[7];
    const float* bhn    = (const float*)d_in[8];
    const float* W_out  = (const float*)d_in[9];
    const float* b_out  = (const float*)d_in[10];

    float* out    = (float*)d_out;
    float* hfinal = out;                        // [512, 128]
    float* q      = out + (size_t)BATCH * HID;  // [512, 512, 18]

    void *p_ys, *p_gi;
    cudaGetSymbolAddress(&p_ys, g_ys);
    cudaGetSymbolAddress(&p_gi, g_gi);
    float* embys = (float*)p_ys;   // emb, later ys
    float* gi    = (float*)p_gi;

    const int gemm_smem  = (64 * 129 + 128 * 128) * 4;       // 98816 B
    const int qproj_smem = (128 * 129 + 128 * 20 + 18) * 4;  // 76360 B
    cudaFuncSetAttribute(gemm8x8<true>,
        cudaFuncAttributeMaxDynamicSharedMemorySize, gemm_smem);
    cudaFuncSetAttribute(gemm8x8<false>,
        cudaFuncAttributeMaxDynamicSharedMemorySize, gemm_smem);
    cudaFuncSetAttribute(qproj_kernel,
        cudaFuncAttributeMaxDynamicSharedMemorySize, qproj_smem);

    // emb = relu(obs @ W_emb + b_emb)
    gemm8x8<true><<<dim3(TBROWS / 64, 1), 128, gemm_smem>>>(obs, W_emb, b_emb, embys, 128);
    // gi = emb @ Wi + bi
    gemm8x8<false><<<dim3(TBROWS / 64, 3), 128, gemm_smem>>>(embys, Wi, bi, gi, 384);
    // GRU scan (Wh in registers; writes ys over emb buffer)
    scan_kernel<<<BATCH / 4, 384>>>(hidden, gi, dones, Wh, bhn, hfinal, embys);
    // q = ys @ W_out + b_out
    qproj_kernel<<<TBROWS / 128, 128, qproj_smem>>>(embys, W_out, b_out, q);
}

// round 5
// speedup vs baseline: 1.5066x; 1.1205x over previous
#include <cuda_runtime.h>
#include <cstdint>

#define T_STEPS 512
#define BATCH   512
#define HID     128
#define ACT     18
#define TBROWS  (T_STEPS * BATCH)   // 262144

// Scratch (device globals: allocation is forbidden)
__device__ float g_ys[(size_t)TBROWS * HID];         // emb, then ys (reused)
__device__ float g_gi [(size_t)TBROWS * 3 * HID];    // gi

typedef unsigned long long u64;

__device__ __forceinline__ u64 pk2(float x) {
    u64 d; asm("mov.b64 %0, {%1,%1};" : "=l"(d) : "f"(x)); return d;
}
__device__ __forceinline__ u64 pk2two(float a, float b) {
    u64 d; asm("mov.b64 %0, {%1,%2};" : "=l"(d) : "f"(a), "f"(b)); return d;
}
__device__ __forceinline__ void fma2(u64 &c, u64 a, u64 b) {
    asm("fma.rn.f32x2 %0, %1, %2, %3;" : "=l"(c) : "l"(a), "l"(b), "l"(c));
}
__device__ __forceinline__ float2 unpk(u64 v) {
    float2 f; asm("mov.b64 {%0,%1}, %2;" : "=f"(f.x), "=f"(f.y) : "l"(v)); return f;
}
__device__ __forceinline__ void cp_async16(uint32_t dst, const void* src) {
    asm volatile("cp.async.ca.shared.global [%0], [%1], 16;" :: "r"(dst), "l"(src));
}

// ---------------------------------------------------------------------------
// GEMM: C[M,N] = act(A[M,128] @ W[128,N] + bias[N]).
// CTA tile 64x128, 128 threads, thread tile 8x8, f32x2 accumulators.
// Inner loop blocked by 4 k: A read as float4 along k (pitch 132).
// ---------------------------------------------------------------------------
template<bool RELU>
__global__ __launch_bounds__(128, 2) void gemm8x8(
    const float* __restrict__ A, const float* __restrict__ W,
    const float* __restrict__ bias, float* __restrict__ C, int N)
{
    extern __shared__ float sm[];
    float* As = sm;             // [64][132]
    float* Bs = sm + 64 * 132;  // [128][128]

    const int m0  = blockIdx.x * 64;
    const int n0  = blockIdx.y * 128;
    const int tid = threadIdx.x;

    for (int i = tid; i < 2048; i += 128) {
        int m = i >> 5, kv = (i & 31) << 2;
        *(float4*)(As + m * 132 + kv) =
            *(const float4*)(A + (size_t)(m0 + m) * 128 + kv);
    }
    for (int i = tid; i < 4096; i += 128) {
        int k = i >> 5, nv = (i & 31) << 2;
        *(float4*)(Bs + k * 128 + nv) =
            *(const float4*)(W + (size_t)k * N + n0 + nv);
    }
    __syncthreads();

    const int tx = tid & 15;
    const int ty = tid >> 4;

    u64 acc[8][4];
    #pragma unroll
    for (int r = 0; r < 8; ++r)
        #pragma unroll
        for (int c = 0; c < 4; ++c) acc[r][c] = 0ull;

    const float* ap = As + ty * 8 * 132;
    const u64*   bp = (const u64*)Bs + tx * 4;   // row stride 64 u64

    #pragma unroll
    for (int k4 = 0; k4 < 128; k4 += 4) {
        float4 av[8];
        #pragma unroll
        for (int r = 0; r < 8; ++r)
            av[r] = *(const float4*)(ap + r * 132 + k4);
        #pragma unroll
        for (int kk = 0; kk < 4; ++kk) {
            ulonglong2 b01 = *(const ulonglong2*)(bp + (size_t)(k4 + kk) * 64);
            ulonglong2 b23 = *(const ulonglong2*)(bp + (size_t)(k4 + kk) * 64 + 2);
            #pragma unroll
            for (int r = 0; r < 8; ++r) {
                u64 ad = pk2(((const float*)&av[r])[kk]);
                fma2(acc[r][0], ad, b01.x);
                fma2(acc[r][1], ad, b01.y);
                fma2(acc[r][2], ad, b23.x);
                fma2(acc[r][3], ad, b23.y);
            }
        }
    }

    float bb[8];
    {
        float4 b0 = *(const float4*)(bias + n0 + tx * 8);
        float4 b1 = *(const float4*)(bias + n0 + tx * 8 + 4);
        bb[0]=b0.x; bb[1]=b0.y; bb[2]=b0.z; bb[3]=b0.w;
        bb[4]=b1.x; bb[5]=b1.y; bb[6]=b1.z; bb[7]=b1.w;
    }
    #pragma unroll
    for (int r = 0; r < 8; ++r) {
        float2 f0 = unpk(acc[r][0]), f1 = unpk(acc[r][1]);
        float2 f2 = unpk(acc[r][2]), f3 = unpk(acc[r][3]);
        float v[8] = { f0.x, f0.y, f1.x, f1.y, f2.x, f2.y, f3.x, f3.y };
        #pragma unroll
        for (int j = 0; j < 8; ++j) {
            v[j] += bb[j];
            if (RELU) v[j] = fmaxf(v[j], 0.0f);
        }
        float* cp = C + (size_t)(m0 + ty * 8 + r) * N + n0 + tx * 8;
        *(float4*)(cp)     = make_float4(v[0], v[1], v[2], v[3]);
        *(float4*)(cp + 4) = make_float4(v[4], v[5], v[6], v[7]);
    }
}

// ---------------------------------------------------------------------------
// Scan: 128 CTAs x 384 threads, 4 batch rows per CTA.
// Wh column tid in registers. gi staged via cp.async double buffer (keeps the
// register file clear so ptxas can pipeline the h4 broadcast LDS).
// ---------------------------------------------------------------------------
__device__ __forceinline__ float sigf(float x) {
    return __fdividef(1.0f, 1.0f + __expf(-x));
}
__device__ __forceinline__ float tanhfast(float x) {
    return __fdividef(2.0f, 1.0f + __expf(-2.0f * x)) - 1.0f;
}

__global__ __launch_bounds__(384, 1) void scan_kernel(
    const float* __restrict__ hidden, const float* __restrict__ gi_all,
    const int* __restrict__ dones,
    const float* __restrict__ Wh, const float* __restrict__ bhn,
    float* __restrict__ hfinal, float* __restrict__ ys)
{
    __shared__ float4 h4_s[128];       // h of 4 rows per hidden dim
    __shared__ u64    gh01_s[384];     // gh rows 0,1 packed per column
    __shared__ u64    gh23_s[384];     // gh rows 2,3 packed per column
    __shared__ float  bhn_s[128];
    __shared__ float  maskf_s[T_STEPS * 4];   // (1-done) per (t, row)
    __shared__ float  gi_s[2][1536];          // double-buffered gi slice

    const int tid = threadIdx.x;
    const int b0  = blockIdx.x * 4;

    const uint32_t gi_smem = (uint32_t)__cvta_generic_to_shared(&gi_s[0][0])
                             + (uint32_t)tid * 16u;
    const float* gi_src = gi_all + (size_t)b0 * 384 + tid * 4;

    // Kick off gi for t=0 immediately
    cp_async16(gi_smem, gi_src);
    asm volatile("cp.async.commit_group;");

    // Wh column tid -> registers (coalesced LDG across threads)
    float w[128];
    #pragma unroll
    for (int k = 0; k < 128; ++k)
        w[k] = Wh[(size_t)k * 384 + tid];

    if (tid < 128) bhn_s[tid] = bhn[tid];
    for (int i = tid; i < T_STEPS * 4; i += 384) {
        int t = i >> 2, r = i & 3;
        maskf_s[i] = dones[t * BATCH + b0 + r] ? 0.0f : 1.0f;
    }
    for (int idx = tid; idx < 512; idx += 384) {
        int r = idx >> 7, i = idx & 127;
        ((float*)&h4_s[i])[r] = hidden[(size_t)(b0 + r) * 128 + i];
    }
    __syncthreads();

    const int rr0 = tid >> 7;
    const int i0  = tid & 127;

    for (int t = 0; t < T_STEPS; ++t) {
        // issue cp.async for t+1 (lands during our matvec)
        if (t + 1 < T_STEPS) {
            cp_async16(gi_smem + (((t + 1) & 1) ? 6144u : 0u),
                       gi_src + (size_t)(t + 1) * (BATCH * 384));
            asm volatile("cp.async.commit_group;");
        }

        // matvec: gh[:, tid] = h4 . w  (w in registers, h4 broadcast LDS)
        u64 a01 = 0ull, a23 = 0ull;
        #pragma unroll
        for (int k = 0; k < 128; ++k) {
            ulonglong2 hv = *(const ulonglong2*)&h4_s[k];
            u64 wd = pk2(w[k]);
            fma2(a01, hv.x, wd);
            fma2(a23, hv.y, wd);
        }
        gh01_s[tid] = a01;
        gh23_s[tid] = a23;

        if (t + 1 < T_STEPS) {
            asm volatile("cp.async.wait_group 1;");   // gi[t] landed
        } else {
            asm volatile("cp.async.wait_group 0;");
        }
        __syncthreads();   // (A) gh + gi[t] visible; matvec reads of h4 done

        const float* gbuf = gi_s[t & 1];

        // gates slot 0: item (rr0, i0)
        {
            const float mk = maskf_s[t * 4 + rr0];
            const float* gb = gbuf + rr0 * 384;
            const float* g = (rr0 < 2) ? (const float*)gh01_s : (const float*)gh23_s;
            const int sub = rr0 & 1;
            float ghr = g[2 * i0 + sub];
            float ghz = g[2 * (128 + i0) + sub];
            float ghn = g[2 * (256 + i0) + sub];
            float rg = sigf(gb[i0] + mk * ghr);
            float zg = sigf(gb[128 + i0] + mk * ghz);
            float nv = tanhfast(gb[256 + i0] + rg * (mk * ghn + bhn_s[i0]));
            float* hp = ((float*)&h4_s[i0]) + rr0;
            float hn = (1.0f - zg) * nv + zg * (*hp * mk);
            *hp = hn;
            ys[((size_t)t * BATCH + b0 + rr0) * 128 + i0] = hn;
        }
        // gates slot 1: row 3
        if (tid < 128) {
            const float mk = maskf_s[t * 4 + 3];
            const float* gb = gbuf + 3 * 384;
            const float* g = (const float*)gh23_s;
            float ghr = g[2 * tid + 1];
            float ghz = g[2 * (128 + tid) + 1];
            float ghn = g[2 * (256 + tid) + 1];
            float rg = sigf(gb[tid] + mk * ghr);
            float zg = sigf(gb[128 + tid] + mk * ghz);
            float nv = tanhfast(gb[256 + tid] + rg * (mk * ghn + bhn_s[tid]));
            float* hp = ((float*)&h4_s[tid]) + 3;
            float hn = (1.0f - zg) * nv + zg * (*hp * mk);
            *hp = hn;
            ys[((size_t)t * BATCH + b0 + 3) * 128 + tid] = hn;
        }
        __syncthreads();   // (B) h4 updated before next matvec
    }

    for (int idx = tid; idx < 512; idx += 384) {
        int r = idx >> 7, i = idx & 127;
        hfinal[(size_t)(b0 + r) * 128 + i] = ((float*)&h4_s[i])[r];
    }
}

// ---------------------------------------------------------------------------
// q projection: q[M,18] = ys[M,128] @ W_out[128,18] + b_out.
// 128 rows/CTA, 256 threads: 2-way split-k per row, smem combine.
// ---------------------------------------------------------------------------
__global__ __launch_bounds__(256, 2) void qproj_kernel(
    const float* __restrict__ ys, const float* __restrict__ Wo,
    const float* __restrict__ bo, float* __restrict__ q)
{
    extern __shared__ float sm[];
    float* As   = sm;                 // [128][129]
    float* Wo_s = sm + 128 * 129;     // [128][20]
    float* bo_s = Wo_s + 128 * 20;    // [18], pad to 32
    u64*   Ps   = (u64*)(bo_s + 32);  // [128][10] partials (upper k-half)

    const int tid = threadIdx.x;
    const size_t m0 = (size_t)blockIdx.x * 128;

    for (int i = tid; i < 4096; i += 256) {
        int m = i >> 5, kv = (i & 31) << 2;
        float4 v = *(const float4*)(ys + (m0 + m) * 128 + kv);
        float* d = As + m * 129 + kv;
        d[0] = v.x; d[1] = v.y; d[2] = v.z; d[3] = v.w;
    }
    for (int i = tid; i < 128 * 18; i += 256)
        Wo_s[(i / 18) * 20 + (i % 18)] = Wo[i];
    if (tid < 18) bo_s[tid] = bo[tid];
    __syncthreads();

    const int row = tid & 127;
    const int kh  = (tid >> 7) * 64;   // 0 or 64

    u64 acc[9];
    #pragma unroll
    for (int p = 0; p < 9; ++p)
        acc[p] = (kh == 0) ? pk2two(bo_s[2 * p], bo_s[2 * p + 1]) : 0ull;

    const float* ap = As + row * 129 + kh;
    const float* wp = Wo_s + kh * 20;
    #pragma unroll 4
    for (int k = 0; k < 64; ++k) {
        u64 hd = pk2(ap[k]);
        const u64* wrow = (const u64*)(wp + k * 20);
        #pragma unroll
        for (int p = 0; p < 9; ++p) fma2(acc[p], hd, wrow[p]);
    }

    if (kh) {
        #pragma unroll
        for (int p = 0; p < 9; ++p) Ps[row * 10 + p] = acc[p];
    }
    __syncthreads();

    if (!kh) {
        float* qp = q + (m0 + row) * ACT;
        #pragma unroll
        for (int p = 0; p < 9; ++p) {
            float2 a = unpk(acc[p]);
            float2 b = unpk(Ps[row * 10 + p]);
            *(float2*)(qp + 2 * p) = make_float2(a.x + b.x, a.y + b.y);
        }
    }
}

// ---------------------------------------------------------------------------
extern "C" void kernel_launch(void* const* d_in, const int* in_sizes, int n_in,
                              void* d_out, int out_size)
{
    const float* hidden = (const float*)d_in[0];
    const float* obs    = (const float*)d_in[1];
    const int*   dones  = (const int*)d_in[2];
    const float* W_emb  = (const float*)d_in[3];
    const float* b_emb  = (const float*)d_in[4];
    const float* Wi     = (const float*)d_in[5];
    const float* bi     = (const float*)d_in[6];
    const float* Wh     = (const float*)d_in[7];
    const float* bhn    = (const float*)d_in[8];
    const float* W_out  = (const float*)d_in[9];
    const float* b_out  = (const float*)d_in[10];

    float* out    = (float*)d_out;
    float* hfinal = out;                        // [512, 128]
    float* q      = out + (size_t)BATCH * HID;  // [512, 512, 18]

    void *p_ys, *p_gi;
    cudaGetSymbolAddress(&p_ys, g_ys);
    cudaGetSymbolAddress(&p_gi, g_gi);
    float* embys = (float*)p_ys;   // emb, later ys
    float* gi    = (float*)p_gi;

    const int gemm_smem  = (64 * 132 + 128 * 128) * 4;                // 99328 B
    const int qproj_smem = (128 * 129 + 128 * 20 + 32) * 4 + 128 * 10 * 8; // ~86688 B
    cudaFuncSetAttribute(gemm8x8<true>,
        cudaFuncAttributeMaxDynamicSharedMemorySize, gemm_smem);
    cudaFuncSetAttribute(gemm8x8<false>,
        cudaFuncAttributeMaxDynamicSharedMemorySize, gemm_smem);
    cudaFuncSetAttribute(qproj_kernel,
        cudaFuncAttributeMaxDynamicSharedMemorySize, qproj_smem);

    // emb = relu(obs @ W_emb + b_emb)
    gemm8x8<true><<<dim3(TBROWS / 64, 1), 128, gemm_smem>>>(obs, W_emb, b_emb, embys, 128);
    // gi = emb @ Wi + bi
    gemm8x8<false><<<dim3(TBROWS / 64, 3), 128, gemm_smem>>>(embys, Wi, bi, gi, 384);
    // GRU scan (Wh in registers, gi via cp.async; writes ys over emb buffer)
    scan_kernel<<<BATCH / 4, 384>>>(hidden, gi, dones, Wh, bhn, hfinal, embys);
    // q = ys @ W_out + b_out
    qproj_kernel<<<TBROWS / 128, 256, qproj_smem>>>(embys, W_out, b_out, q);
}